// round 3
// baseline (speedup 1.0000x reference)
#include <cuda_runtime.h>

#define N_NODES 60000
#define N_EDGES 1200000
#define D 64
#define SCAN_B 1024
#define MAX_BLOCKS_SCAN 64   // ceil(60000/1024) = 59

// ---------------- scratch (no allocations allowed) ----------------
__device__ int   g_deg[N_NODES];
__device__ int   g_ptr[N_NODES + 1];
__device__ int   g_fill[N_NODES];
__device__ int   g_edges[N_EDGES];     // src ids sorted by dst bucket
__device__ int   g_bsums[MAX_BLOCKS_SCAN];
__device__ int   g_boffs[MAX_BLOCKS_SCAN];
__device__ float g_dinv[N_NODES];
__device__ float g_xs0[N_NODES * D];   // X0 * dinv
__device__ float g_xs1[N_NODES * D];   // X1 * dinv
__device__ float g_x1 [N_NODES * D];   // X1 raw

// ---------------- CSR build ----------------
__global__ void k_zero_deg(int n) {
    int i = blockIdx.x * blockDim.x + threadIdx.x;
    if (i < n) g_deg[i] = 0;
}

__global__ void k_count(const int* __restrict__ dst, int e) {
    int i = blockIdx.x * blockDim.x + threadIdx.x;
    if (i < e) atomicAdd(&g_deg[dst[i]], 1);
}

__global__ void k_scan_block(int n) {
    __shared__ int sh[SCAN_B];
    int t = threadIdx.x;
    int i = blockIdx.x * SCAN_B + t;
    int v = (i < n) ? g_deg[i] : 0;
    sh[t] = v;
    __syncthreads();
    for (int off = 1; off < SCAN_B; off <<= 1) {
        int add = (t >= off) ? sh[t - off] : 0;
        __syncthreads();
        sh[t] += add;
        __syncthreads();
    }
    if (i < n) g_ptr[i] = sh[t] - v;            // exclusive within block
    if (t == SCAN_B - 1) g_bsums[blockIdx.x] = sh[t];
}

__global__ void k_scan_sums(int nb) {
    __shared__ int sh[MAX_BLOCKS_SCAN];
    int t = threadIdx.x;
    int v = (t < nb) ? g_bsums[t] : 0;
    sh[t] = v;
    __syncthreads();
    for (int off = 1; off < MAX_BLOCKS_SCAN; off <<= 1) {
        int add = (t >= off) ? sh[t - off] : 0;
        __syncthreads();
        sh[t] += add;
        __syncthreads();
    }
    sh[t] -= v;                                 // exclusive
    __syncthreads();
    if (t < nb) g_boffs[t] = sh[t];
}

__global__ void k_finalize(int n, int e) {
    int i = blockIdx.x * blockDim.x + threadIdx.x;
    if (i < n) {
        int p = g_ptr[i] + g_boffs[i / SCAN_B];
        g_ptr[i]  = p;
        g_fill[i] = p;
        int d = g_deg[i];
        g_dinv[i] = rsqrtf((float)(d > 0 ? d : 1));
        if (i == 0) g_ptr[n] = e;
    }
}

__global__ void k_fill(const int* __restrict__ src, const int* __restrict__ dst, int e) {
    int i = blockIdx.x * blockDim.x + threadIdx.x;
    if (i < e) {
        int d   = dst[i];
        int pos = atomicAdd(&g_fill[d], 1);
        g_edges[pos] = src[i];
    }
}

// ---------------- feature kernels ----------------
// xs0 = feat * dinv[row]; out[:, 0:64] = relu(feat)
__global__ void k_scale0(const float* __restrict__ feat, float* __restrict__ out, int n) {
    int idx = blockIdx.x * blockDim.x + threadIdx.x;   // over n*32 float2 units
    if (idx < n * 32) {
        int row  = idx >> 5;
        int lane = idx & 31;
        float2 f = ((const float2*)feat)[idx];
        float  di = g_dinv[row];
        float2 s = make_float2(f.x * di, f.y * di);
        ((float2*)g_xs0)[idx] = s;
        float2 r = make_float2(fmaxf(f.x, 0.f), fmaxf(f.y, 0.f));
        ((float2*)(out + (size_t)row * 192))[lane] = r;
    }
}

// warp-per-node gather of xs rows over CSR edge list
__device__ __forceinline__ float2 gather_row(int node, int lane, const float2* __restrict__ xs) {
    int beg = __ldg(&g_ptr[node]);
    int end = __ldg(&g_ptr[node + 1]);
    float2 acc = make_float2(0.f, 0.f);
    for (int j = beg; j < end; j += 32) {
        int idx = j + lane;
        int s   = (idx < end) ? __ldg(&g_edges[idx]) : 0;
        int cnt = min(32, end - j);
        #pragma unroll 4
        for (int k = 0; k < cnt; k++) {
            int sk = __shfl_sync(0xffffffffu, s, k);
            float2 v = __ldg(&xs[sk * 32 + lane]);
            acc.x += v.x;
            acc.y += v.y;
        }
    }
    return acc;
}

// X1 = -rn*h + (rn-1)*X0 ; writes g_x1, g_xs1, out[:,64:128]=relu(X1)
__global__ void k_apply1(const float* __restrict__ feat, const float* __restrict__ lam,
                         float* __restrict__ out, int n) {
    int w    = (blockIdx.x * blockDim.x + threadIdx.x) >> 5;
    int lane = threadIdx.x & 31;
    if (w >= n) return;
    float rn = 2.0f / __ldg(lam);
    float2 acc = gather_row(w, lane, (const float2*)g_xs0);
    float di = g_dinv[w];
    float2 x0 = ((const float2*)feat)[w * 32 + lane];
    float2 x1;
    x1.x = -rn * (acc.x * di) + x0.x * (rn - 1.0f);
    x1.y = -rn * (acc.y * di) + x0.y * (rn - 1.0f);
    ((float2*)g_x1)[w * 32 + lane] = x1;
    ((float2*)g_xs1)[w * 32 + lane] = make_float2(x1.x * di, x1.y * di);
    float2 r = make_float2(fmaxf(x1.x, 0.f), fmaxf(x1.y, 0.f));
    ((float2*)(out + (size_t)w * 192 + 64))[lane] = r;
}

// X2 = -2rn*h + 2(rn-1)*X1 - X0 ; writes out[:,128:192]=relu(X2)
__global__ void k_apply2(const float* __restrict__ feat, const float* __restrict__ lam,
                         float* __restrict__ out, int n) {
    int w    = (blockIdx.x * blockDim.x + threadIdx.x) >> 5;
    int lane = threadIdx.x & 31;
    if (w >= n) return;
    float rn = 2.0f / __ldg(lam);
    float2 acc = gather_row(w, lane, (const float2*)g_xs1);
    float di = g_dinv[w];
    float2 x0 = ((const float2*)feat)[w * 32 + lane];
    float2 x1 = ((const float2*)g_x1)[w * 32 + lane];
    float2 x2;
    x2.x = -2.0f * rn * (acc.x * di) + 2.0f * (rn - 1.0f) * x1.x - x0.x;
    x2.y = -2.0f * rn * (acc.y * di) + 2.0f * (rn - 1.0f) * x1.y - x0.y;
    float2 r = make_float2(fmaxf(x2.x, 0.f), fmaxf(x2.y, 0.f));
    ((float2*)(out + (size_t)w * 192 + 128))[lane] = r;
}

// ---------------- launch ----------------
extern "C" void kernel_launch(void* const* d_in, const int* in_sizes, int n_in,
                              void* d_out, int out_size) {
    const float* feat = (const float*)d_in[0];
    const int*   src  = (const int*)d_in[1];
    const int*   dst  = (const int*)d_in[2];
    const float* lam  = (const float*)d_in[3];
    float* out = (float*)d_out;

    int n = in_sizes[0] / D;     // 60000
    int e = in_sizes[1];         // 1200000
    int nb = (n + SCAN_B - 1) / SCAN_B;

    k_zero_deg <<<(n + 255) / 256, 256>>>(n);
    k_count    <<<(e + 255) / 256, 256>>>(dst, e);
    k_scan_block<<<nb, SCAN_B>>>(n);
    k_scan_sums<<<1, MAX_BLOCKS_SCAN>>>(nb);
    k_finalize <<<(n + 255) / 256, 256>>>(n, e);
    k_fill     <<<(e + 255) / 256, 256>>>(src, dst, e);

    int fthreads = n * 32;       // one thread per float2
    k_scale0<<<(fthreads + 255) / 256, 256>>>(feat, out, n);
    k_apply1<<<(fthreads + 255) / 256, 256>>>(feat, lam, out, n);
    k_apply2<<<(fthreads + 255) / 256, 256>>>(feat, lam, out, n);
}

// round 4
// speedup vs baseline: 1.1110x; 1.1110x over previous
#include <cuda_runtime.h>

#define N_NODES 60000
#define N_EDGES 1200000
#define D 64
#define SCAN_B 1024
#define MAX_BLOCKS_SCAN 64   // ceil(60000/1024) = 59

// ---------------- scratch (no allocations allowed) ----------------
__device__ int   g_deg[N_NODES];
__device__ int   g_ptr[N_NODES + 1];
__device__ int   g_fill[N_NODES];
__device__ int   g_edges[N_EDGES];     // src ids sorted by dst bucket
__device__ int   g_bsums[MAX_BLOCKS_SCAN];
__device__ float g_dinv[N_NODES];      // 1/sqrt(max(deg,1))
__device__ float g_dsq [N_NODES];      // sqrt(max(deg,1))
__device__ float g_xs0[N_NODES * D];   // X0 * dinv
__device__ float g_xs1[N_NODES * D];   // X1 * dinv

// ---------------- CSR build ----------------
__global__ void k_zero_deg(int n) {
    int i = blockIdx.x * blockDim.x + threadIdx.x;
    if (i < n) g_deg[i] = 0;
}

__global__ void k_count(const int* __restrict__ dst, int e) {
    int i = blockIdx.x * blockDim.x + threadIdx.x;
    if (i < e) atomicAdd(&g_deg[dst[i]], 1);
}

__global__ void k_scan_block(int n) {
    __shared__ int sh[SCAN_B];
    int t = threadIdx.x;
    int i = blockIdx.x * SCAN_B + t;
    int v = (i < n) ? g_deg[i] : 0;
    sh[t] = v;
    __syncthreads();
    for (int off = 1; off < SCAN_B; off <<= 1) {
        int add = (t >= off) ? sh[t - off] : 0;
        __syncthreads();
        sh[t] += add;
        __syncthreads();
    }
    if (i < n) g_ptr[i] = sh[t] - v;            // exclusive within block
    if (t == SCAN_B - 1) g_bsums[blockIdx.x] = sh[t];
}

// finalize: every block redundantly scans the (<=59) block sums in shared,
// then applies the global offset; computes dinv/dsq; inits g_fill.
__global__ void k_finalize(int n, int e, int nb) {
    __shared__ int sh[MAX_BLOCKS_SCAN];
    int t = threadIdx.x;
    if (t < MAX_BLOCKS_SCAN) sh[t] = (t < nb) ? g_bsums[t] : 0;
    __syncthreads();
    for (int off = 1; off < MAX_BLOCKS_SCAN; off <<= 1) {
        int add = (t < MAX_BLOCKS_SCAN && t >= off) ? sh[t - off] : 0;
        __syncthreads();
        if (t < MAX_BLOCKS_SCAN) sh[t] += add;   // inclusive scan of bsums
        __syncthreads();
    }
    int i = blockIdx.x * blockDim.x + t;
    if (i < n) {
        int b    = i / SCAN_B;
        int boff = (b == 0) ? 0 : sh[b - 1];
        int p = g_ptr[i] + boff;
        g_ptr[i]  = p;
        g_fill[i] = p;
        int d = g_deg[i];
        float df = (float)(d > 0 ? d : 1);
        g_dinv[i] = rsqrtf(df);
        g_dsq[i]  = sqrtf(df);
        if (i == 0) g_ptr[n] = e;
    }
}

// fused: edge bucket fill (scattered atomics) + xs0/out0 streaming
__global__ void k_fill_scale(const int* __restrict__ src, const int* __restrict__ dst,
                             const float* __restrict__ feat, float* __restrict__ out,
                             int e, int n) {
    int i = blockIdx.x * blockDim.x + threadIdx.x;
    if (i < e) {
        int d   = dst[i];
        int pos = atomicAdd(&g_fill[d], 1);
        g_edges[pos] = src[i];
    }
    if (i < n * 32) {                      // one float2 per thread
        int row  = i >> 5;
        int lane = i & 31;
        float2 f = ((const float2*)feat)[i];
        float  di = g_dinv[row];
        ((float2*)g_xs0)[i] = make_float2(f.x * di, f.y * di);
        ((float2*)(out + (size_t)row * 192))[lane] =
            make_float2(fmaxf(f.x, 0.f), fmaxf(f.y, 0.f));
    }
}

// ---------------- gather applies ----------------
__device__ __forceinline__ float2 gather_row(int node, int lane, const float2* __restrict__ xs) {
    int beg = __ldg(&g_ptr[node]);
    int end = __ldg(&g_ptr[node + 1]);
    float2 acc = make_float2(0.f, 0.f);
    for (int j = beg; j < end; j += 32) {
        int idx = j + lane;
        int s   = (idx < end) ? __ldg(&g_edges[idx]) : 0;
        int cnt = min(32, end - j);
        #pragma unroll 8
        for (int k = 0; k < cnt; k++) {
            int sk = __shfl_sync(0xffffffffu, s, k);
            float2 v = __ldg(&xs[sk * 32 + lane]);
            acc.x += v.x;
            acc.y += v.y;
        }
    }
    return acc;
}

// X1 = -rn*h + (rn-1)*X0 ; writes xs1 = X1*dinv, out[:,64:128]=relu(X1)
__global__ void k_apply1(const float* __restrict__ feat, const float* __restrict__ lam,
                         float* __restrict__ out, int n) {
    int w    = (blockIdx.x * blockDim.x + threadIdx.x) >> 5;
    int lane = threadIdx.x & 31;
    if (w >= n) return;
    float rn = 2.0f / __ldg(lam);
    float2 acc = gather_row(w, lane, (const float2*)g_xs0);
    float di = g_dinv[w];
    float2 x0 = ((const float2*)feat)[w * 32 + lane];
    float2 x1;
    x1.x = -rn * (acc.x * di) + x0.x * (rn - 1.0f);
    x1.y = -rn * (acc.y * di) + x0.y * (rn - 1.0f);
    ((float2*)g_xs1)[w * 32 + lane] = make_float2(x1.x * di, x1.y * di);
    ((float2*)(out + (size_t)w * 192 + 64))[lane] =
        make_float2(fmaxf(x1.x, 0.f), fmaxf(x1.y, 0.f));
}

// X2 = -2rn*h + 2(rn-1)*X1 - X0 ; X1 recovered as xs1*sqrt(deg)
__global__ void k_apply2(const float* __restrict__ feat, const float* __restrict__ lam,
                         float* __restrict__ out, int n) {
    int w    = (blockIdx.x * blockDim.x + threadIdx.x) >> 5;
    int lane = threadIdx.x & 31;
    if (w >= n) return;
    float rn = 2.0f / __ldg(lam);
    float2 acc = gather_row(w, lane, (const float2*)g_xs1);
    float di = g_dinv[w];
    float ds = g_dsq[w];
    float2 x0  = ((const float2*)feat)[w * 32 + lane];
    float2 xs1 = ((const float2*)g_xs1)[w * 32 + lane];
    float2 x1  = make_float2(xs1.x * ds, xs1.y * ds);   // exact: dsq*dinv == 1
    float2 x2;
    x2.x = -2.0f * rn * (acc.x * di) + 2.0f * (rn - 1.0f) * x1.x - x0.x;
    x2.y = -2.0f * rn * (acc.y * di) + 2.0f * (rn - 1.0f) * x1.y - x0.y;
    ((float2*)(out + (size_t)w * 192 + 128))[lane] =
        make_float2(fmaxf(x2.x, 0.f), fmaxf(x2.y, 0.f));
}

// ---------------- launch ----------------
extern "C" void kernel_launch(void* const* d_in, const int* in_sizes, int n_in,
                              void* d_out, int out_size) {
    const float* feat = (const float*)d_in[0];
    const int*   src  = (const int*)d_in[1];
    const int*   dst  = (const int*)d_in[2];
    const float* lam  = (const float*)d_in[3];
    float* out = (float*)d_out;

    int n = in_sizes[0] / D;     // 60000
    int e = in_sizes[1];         // 1200000
    int nb = (n + SCAN_B - 1) / SCAN_B;

    k_zero_deg  <<<(n + 255) / 256, 256>>>(n);
    k_count     <<<(e + 255) / 256, 256>>>(dst, e);
    k_scan_block<<<nb, SCAN_B>>>(n);
    k_finalize  <<<(n + 255) / 256, 256>>>(n, e, nb);

    int fmax = (n * 32 > e) ? n * 32 : e;
    k_fill_scale<<<(fmax + 255) / 256, 256>>>(src, dst, feat, out, e, n);

    int fthreads = n * 32;
    k_apply1<<<(fthreads + 255) / 256, 256>>>(feat, lam, out, n);
    k_apply2<<<(fthreads + 255) / 256, 256>>>(feat, lam, out, n);
}

// round 5
// speedup vs baseline: 1.1867x; 1.0681x over previous
#include <cuda_runtime.h>
#include <cuda_fp16.h>

#define N_NODES 60000
#define N_EDGES 1200000
#define D 64
#define SCAN_B 1024
#define MAX_BLOCKS_SCAN 64   // ceil(60000/1024) = 59

// ---------------- scratch (no allocations allowed) ----------------
__device__ int     g_deg[N_NODES];
__device__ int     g_ptr[N_NODES + 1];
__device__ int     g_fill[N_NODES];
__device__ int     g_edges[N_EDGES];     // src ids sorted by dst bucket
__device__ int     g_bsums[MAX_BLOCKS_SCAN];
__device__ float   g_dinv[N_NODES];      // 1/sqrt(max(deg,1))
__device__ float   g_dsq [N_NODES];      // sqrt(max(deg,1))
__device__ __half2 g_xs0[N_NODES * 32];  // X0 * dinv   (fp16, 2 feats/lane)
__device__ __half2 g_xs1[N_NODES * 32];  // X1 * dinv   (fp16)

// ---------------- CSR build ----------------
__global__ void k_zero_deg(int n) {
    int i = blockIdx.x * blockDim.x + threadIdx.x;
    if (i < n) g_deg[i] = 0;
}

__global__ void k_count(const int* __restrict__ dst, int e) {
    int i = blockIdx.x * blockDim.x + threadIdx.x;
    if (i < e) atomicAdd(&g_deg[dst[i]], 1);
}

__global__ void k_scan_block(int n) {
    __shared__ int sh[SCAN_B];
    int t = threadIdx.x;
    int i = blockIdx.x * SCAN_B + t;
    int v = (i < n) ? g_deg[i] : 0;
    sh[t] = v;
    __syncthreads();
    for (int off = 1; off < SCAN_B; off <<= 1) {
        int add = (t >= off) ? sh[t - off] : 0;
        __syncthreads();
        sh[t] += add;
        __syncthreads();
    }
    if (i < n) g_ptr[i] = sh[t] - v;            // exclusive within block
    if (t == SCAN_B - 1) g_bsums[blockIdx.x] = sh[t];
}

// finalize: every block redundantly scans the (<=59) block sums in shared,
// then applies the global offset; computes dinv/dsq; inits g_fill.
__global__ void k_finalize(int n, int e, int nb) {
    __shared__ int sh[MAX_BLOCKS_SCAN];
    int t = threadIdx.x;
    if (t < MAX_BLOCKS_SCAN) sh[t] = (t < nb) ? g_bsums[t] : 0;
    __syncthreads();
    for (int off = 1; off < MAX_BLOCKS_SCAN; off <<= 1) {
        int add = (t < MAX_BLOCKS_SCAN && t >= off) ? sh[t - off] : 0;
        __syncthreads();
        if (t < MAX_BLOCKS_SCAN) sh[t] += add;   // inclusive scan of bsums
        __syncthreads();
    }
    int i = blockIdx.x * blockDim.x + t;
    if (i < n) {
        int b    = i / SCAN_B;
        int boff = (b == 0) ? 0 : sh[b - 1];
        int p = g_ptr[i] + boff;
        g_ptr[i]  = p;
        g_fill[i] = p;
        int d = g_deg[i];
        float df = (float)(d > 0 ? d : 1);
        g_dinv[i] = rsqrtf(df);
        g_dsq[i]  = sqrtf(df);
        if (i == 0) g_ptr[n] = e;
    }
}

// fused: edge bucket fill (scattered atomics) + xs0/out0 streaming
__global__ void k_fill_scale(const int* __restrict__ src, const int* __restrict__ dst,
                             const float* __restrict__ feat, float* __restrict__ out,
                             int e, int n) {
    int i = blockIdx.x * blockDim.x + threadIdx.x;
    if (i < e) {
        int d   = dst[i];
        int pos = atomicAdd(&g_fill[d], 1);
        g_edges[pos] = src[i];
    }
    if (i < n * 32) {                      // one float2 per thread
        int row  = i >> 5;
        int lane = i & 31;
        float2 f = ((const float2*)feat)[i];
        float  di = g_dinv[row];
        g_xs0[i] = __floats2half2_rn(f.x * di, f.y * di);
        ((float2*)(out + (size_t)row * 192))[lane] =
            make_float2(fmaxf(f.x, 0.f), fmaxf(f.y, 0.f));
    }
}

// ---------------- gather applies (fp16 rows, fp32 accumulate) ----------------
__device__ __forceinline__ float2 gather_row(int node, int lane, const __half2* __restrict__ xs) {
    int beg = __ldg(&g_ptr[node]);
    int end = __ldg(&g_ptr[node + 1]);
    float2 acc = make_float2(0.f, 0.f);
    for (int j = beg; j < end; j += 32) {
        int idx = j + lane;
        int s   = (idx < end) ? __ldg(&g_edges[idx]) : 0;
        int cnt = min(32, end - j);
        #pragma unroll 8
        for (int k = 0; k < cnt; k++) {
            int sk = __shfl_sync(0xffffffffu, s, k);
            float2 v = __half22float2(__ldg(&xs[sk * 32 + lane]));
            acc.x += v.x;
            acc.y += v.y;
        }
    }
    return acc;
}

// X1 = -rn*h + (rn-1)*X0 ; writes xs1 = fp16(X1*dinv), out[:,64:128]=relu(X1)
__global__ void k_apply1(const float* __restrict__ feat, const float* __restrict__ lam,
                         float* __restrict__ out, int n) {
    int w    = (blockIdx.x * blockDim.x + threadIdx.x) >> 5;
    int lane = threadIdx.x & 31;
    if (w >= n) return;
    float rn = 2.0f / __ldg(lam);
    float2 acc = gather_row(w, lane, g_xs0);
    float di = g_dinv[w];
    float2 x0 = ((const float2*)feat)[w * 32 + lane];
    float2 x1;
    x1.x = -rn * (acc.x * di) + x0.x * (rn - 1.0f);
    x1.y = -rn * (acc.y * di) + x0.y * (rn - 1.0f);
    g_xs1[w * 32 + lane] = __floats2half2_rn(x1.x * di, x1.y * di);
    ((float2*)(out + (size_t)w * 192 + 64))[lane] =
        make_float2(fmaxf(x1.x, 0.f), fmaxf(x1.y, 0.f));
}

// X2 = -2rn*h + 2(rn-1)*X1 - X0 ; X1 recovered as fp16(xs1)*sqrt(deg)
__global__ void k_apply2(const float* __restrict__ feat, const float* __restrict__ lam,
                         float* __restrict__ out, int n) {
    int w    = (blockIdx.x * blockDim.x + threadIdx.x) >> 5;
    int lane = threadIdx.x & 31;
    if (w >= n) return;
    float rn = 2.0f / __ldg(lam);
    float2 acc = gather_row(w, lane, g_xs1);
    float di = g_dinv[w];
    float ds = g_dsq[w];
    float2 x0  = ((const float2*)feat)[w * 32 + lane];
    float2 xs1 = __half22float2(g_xs1[w * 32 + lane]);
    float2 x1  = make_float2(xs1.x * ds, xs1.y * ds);
    float2 x2;
    x2.x = -2.0f * rn * (acc.x * di) + 2.0f * (rn - 1.0f) * x1.x - x0.x;
    x2.y = -2.0f * rn * (acc.y * di) + 2.0f * (rn - 1.0f) * x1.y - x0.y;
    ((float2*)(out + (size_t)w * 192 + 128))[lane] =
        make_float2(fmaxf(x2.x, 0.f), fmaxf(x2.y, 0.f));
}

// ---------------- launch ----------------
extern "C" void kernel_launch(void* const* d_in, const int* in_sizes, int n_in,
                              void* d_out, int out_size) {
    const float* feat = (const float*)d_in[0];
    const int*   src  = (const int*)d_in[1];
    const int*   dst  = (const int*)d_in[2];
    const float* lam  = (const float*)d_in[3];
    float* out = (float*)d_out;

    int n = in_sizes[0] / D;     // 60000
    int e = in_sizes[1];         // 1200000
    int nb = (n + SCAN_B - 1) / SCAN_B;

    k_zero_deg  <<<(n + 255) / 256, 256>>>(n);
    k_count     <<<(e + 255) / 256, 256>>>(dst, e);
    k_scan_block<<<nb, SCAN_B>>>(n);
    k_finalize  <<<(n + 255) / 256, 256>>>(n, e, nb);

    int fmax = (n * 32 > e) ? n * 32 : e;
    k_fill_scale<<<(fmax + 255) / 256, 256>>>(src, dst, feat, out, e, n);

    int fthreads = n * 32;
    k_apply1<<<(fthreads + 255) / 256, 256>>>(feat, lam, out, n);
    k_apply2<<<(fthreads + 255) / 256, 256>>>(feat, lam, out, n);
}